// round 7
// baseline (speedup 1.0000x reference)
#include <cuda_runtime.h>

// LocalAttention: 7x7 windowed MHA + depthwise-3x3 LePE on V.
// grid (4096, 12), 64 threads (8 ti x 8 tj). fp32 via fma.rn.f32x2.
// R6 = R3 structure (simple conflict-free indexing) + ex2-domain softmax
//      + LePE folded into att accumulator + launch_bounds(64,9).

typedef unsigned long long u64;

#define QVS 36   // q / v token-major row stride
#define KS  64   // kT row stride (cols 49..63 zero)
#define SS  52   // expS row stride (cols 49..51 zero)

__device__ __forceinline__ u64 pack2(float lo, float hi) {
    u64 r; asm("mov.b64 %0, {%1, %2};" : "=l"(r) : "f"(lo), "f"(hi)); return r;
}
__device__ __forceinline__ void unpack2(u64 v, float &lo, float &hi) {
    asm("mov.b64 {%0, %1}, %2;" : "=f"(lo), "=f"(hi) : "l"(v));
}
__device__ __forceinline__ u64 ffma2(u64 a, u64 b, u64 c) {
    u64 d; asm("fma.rn.f32x2 %0, %1, %2, %3;" : "=l"(d) : "l"(a), "l"(b), "l"(c));
    return d;
}
__device__ __forceinline__ u64 mul2(u64 a, u64 b) {
    u64 d; asm("mul.rn.f32x2 %0, %1, %2;" : "=l"(d) : "l"(a), "l"(b));
    return d;
}
__device__ __forceinline__ float ex2(float x) {
    float y; asm("ex2.approx.ftz.f32 %0, %1;" : "=f"(y) : "f"(x)); return y;
}
__device__ __forceinline__ float rcp(float x) {
    float y; asm("rcp.approx.ftz.f32 %0, %1;" : "=f"(y) : "f"(x)); return y;
}

__global__ __launch_bounds__(64, 9)
void la_kernel(const float* __restrict__ qkv,
               const float* __restrict__ cw,
               const float* __restrict__ cb,
               float* __restrict__ out)
{
    // floats: [0,4064) = union{ qsm[56*36]+kT[32*64] | S[49*52] }
    __shared__ __align__(16) float sm[6256];
    float* qsm = sm;            // [56][QVS] token-major
    float* kT  = sm + 2016;     // [32][KS]
    float* S   = sm;            // [49][SS]  aliases qsm/kT after phase 1
    float* vsm = sm + 4064;     // [52][QVS] rows 49..51 zero
    float* wsm = sm + 5936;     // [9][32]
    float* bsm = sm + 6224;     // [32]

    const int tid = threadIdx.x;
    const int h   = blockIdx.y;
    const int win = blockIdx.x;
    const int b   = win >> 8;
    const int wy  = (win >> 4) & 15;
    const int wx  = win & 15;
    const int tok0  = b * 12544 + wy * 784 + wx * 7;
    const int cbase = h * 32;

    // 1/sqrt(32) * log2(e): softmax runs in log2 domain (ex2.approx)
    const float scale = 0.17677669529663687f * 1.4426950408889634f;
    const size_t koff4 = 19267584ull;           // B*L*DIM/4 (float4 units)

    // zero kT pad cols 49..63
    for (int i = tid; i < 480; i += 64) {
        int d = i / 15;
        kT[d * KS + 49 + (i - d * 15)] = 0.f;
    }
    // zero v pad rows 49..51
    for (int i = tid; i < 108; i += 64) vsm[49 * QVS + i] = 0.f;

    // ---- vectorized load ----
    const float4* qkv4 = (const float4*)qkv;
    for (int idx = tid; idx < 392; idx += 64) {
        int tok = idx >> 3, w = idx & 7;        // d = 4w..4w+3
        int ly = tok / 7, lx = tok - ly * 7;
        size_t g = (size_t)(tok0 + ly * 112 + lx) * 96 + h * 8 + w;
        float4 q4 = qkv4[g];
        float4 k4 = qkv4[g + koff4];
        float4 v4 = qkv4[g + 2 * koff4];
        int d0 = 4 * w;
        q4.x *= scale; q4.y *= scale; q4.z *= scale; q4.w *= scale;
        *(float4*)(qsm + tok * QVS + d0) = q4;
        kT[(d0    ) * KS + tok] = k4.x;
        kT[(d0 + 1) * KS + tok] = k4.y;
        kT[(d0 + 2) * KS + tok] = k4.z;
        kT[(d0 + 3) * KS + tok] = k4.w;
        *(float4*)(vsm + tok * QVS + d0) = v4;
    }
    for (int idx = tid; idx < 288; idx += 64) {
        int tap = idx >> 5, d = idx & 31;
        wsm[tap * 32 + d] = cw[(cbase + d) * 9 + tap];
    }
    if (tid < 32) bsm[tid] = cb[cbase + tid];
    __syncthreads();

    const int ti = tid >> 3;   // 0..7 (rows 7ti..7ti+6; ti==7 pad lane)
    const int tj = tid & 7;    // cols 4tj+{0..3}, 4tj+32+{0..3}

    // ---- phase 1: S = q @ k^T, acc in regs ----
    u64 acc[7][4];
    #pragma unroll
    for (int r = 0; r < 7; r++)
        #pragma unroll
        for (int p = 0; p < 4; p++) acc[r][p] = 0ull;

    {
        const float* qb = qsm + (7 * ti) * QVS;
        const float* kb = kT + (tj << 2);
        #pragma unroll
        for (int dg = 0; dg < 8; dg++) {
            float4 q4[7];
            #pragma unroll
            for (int r = 0; r < 7; r++)
                q4[r] = *(const float4*)(qb + r * QVS + 4 * dg);
            #pragma unroll
            for (int dd = 0; dd < 4; dd++) {
                const float* kr = kb + (4 * dg + dd) * KS;
                ulonglong2 ka = *(const ulonglong2*)(kr);
                ulonglong2 kc = *(const ulonglong2*)(kr + 32);
                #pragma unroll
                for (int r = 0; r < 7; r++) {
                    float qv = (dd == 0) ? q4[r].x : (dd == 1) ? q4[r].y
                             : (dd == 2) ? q4[r].z : q4[r].w;
                    u64 q2 = pack2(qv, qv);
                    acc[r][0] = ffma2(q2, ka.x, acc[r][0]);
                    acc[r][1] = ffma2(q2, ka.y, acc[r][1]);
                    acc[r][2] = ffma2(q2, kc.x, acc[r][2]);
                    acc[r][3] = ffma2(q2, kc.y, acc[r][3]);
                }
            }
        }
    }
    __syncthreads();   // qsm/kT reads done; S may overwrite

    // ---- register softmax (log2 domain) + store expS, keep sum[] in regs ----
    float sumr[7];
    {
        const int c1 = 4 * tj + 32;
        #pragma unroll
        for (int r = 0; r < 7; r++) {
            float s0, s1, s2, s3, s4, s5, s6, s7;
            unpack2(acc[r][0], s0, s1);
            unpack2(acc[r][1], s2, s3);
            unpack2(acc[r][2], s4, s5);
            unpack2(acc[r][3], s6, s7);
            if (c1     >= 49) s4 = -1e30f;
            if (c1 + 1 >= 49) s5 = -1e30f;
            if (c1 + 2 >= 49) s6 = -1e30f;
            if (c1 + 3 >= 49) s7 = -1e30f;
            float m = fmaxf(fmaxf(fmaxf(s0, s1), fmaxf(s2, s3)),
                            fmaxf(fmaxf(s4, s5), fmaxf(s6, s7)));
            m = fmaxf(m, __shfl_xor_sync(0xffffffffu, m, 1));
            m = fmaxf(m, __shfl_xor_sync(0xffffffffu, m, 2));
            m = fmaxf(m, __shfl_xor_sync(0xffffffffu, m, 4));
            float e0 = ex2(s0 - m), e1 = ex2(s1 - m);
            float e2 = ex2(s2 - m), e3 = ex2(s3 - m);
            float e4 = ex2(s4 - m), e5 = ex2(s5 - m);
            float e6 = ex2(s6 - m), e7 = ex2(s7 - m);
            float sum = ((e0 + e1) + (e2 + e3)) + ((e4 + e5) + (e6 + e7));
            sum += __shfl_xor_sync(0xffffffffu, sum, 1);
            sum += __shfl_xor_sync(0xffffffffu, sum, 2);
            sum += __shfl_xor_sync(0xffffffffu, sum, 4);
            sumr[r] = sum;
            if (ti < 7) {
                float* srow = S + (7 * ti + r) * SS;
                *(u64*)(srow + 4 * tj)     = pack2(e0, e1);
                *(u64*)(srow + 4 * tj + 2) = pack2(e2, e3);
                if (c1 < SS) {   // tj<=4: covers cols 32..51 (invalid are 0)
                    *(u64*)(srow + c1)     = pack2(e4, e5);
                    *(u64*)(srow + c1 + 2) = pack2(e6, e7);
                }
            }
        }
    }
    __syncthreads();

    // ---- phase 2: att = (LePE+bias)*sum + expS@V ; out = att * rcp(sum) ----
    {
        u64 att[7][2];
        float4 bb = *(const float4*)(bsm + tj * 4);
        u64 b01 = pack2(bb.x, bb.y), b23 = pack2(bb.z, bb.w);
        #pragma unroll
        for (int r = 0; r < 7; r++) { att[r][0] = b01; att[r][1] = b23; }

        // LePE into att
        #pragma unroll
        for (int ky = 0; ky < 3; ky++) {
            int ny = ti + ky - 1;
            if (ny >= 0 && ny <= 6) {
                #pragma unroll
                for (int kx = 0; kx < 3; kx++) {
                    const ulonglong2 w2 =
                        *(const ulonglong2*)(wsm + (ky * 3 + kx) * 32 + tj * 4);
                    #pragma unroll
                    for (int r = 0; r < 7; r++) {
                        int nx = r + kx - 1;
                        if (nx >= 0 && nx <= 6) {
                            ulonglong2 v2 =
                                *(const ulonglong2*)(vsm + (ny * 7 + nx) * QVS + tj * 4);
                            att[r][0] = ffma2(w2.x, v2.x, att[r][0]);
                            att[r][1] = ffma2(w2.y, v2.y, att[r][1]);
                        }
                    }
                }
            }
        }
        // pre-scale (LePE+bias) by sum so final 1/sum normalizes only attn
        #pragma unroll
        for (int r = 0; r < 7; r++) {
            u64 s2 = pack2(sumr[r], sumr[r]);
            att[r][0] = mul2(att[r][0], s2);
            att[r][1] = mul2(att[r][1], s2);
        }

        // attention: att += expS @ V
        const float* Sb = S + (7 * ti) * SS;
        const float* vb = vsm + (tj << 2);
        #pragma unroll
        for (int kg = 0; kg < 13; kg++) {
            ulonglong2 v0 = *(const ulonglong2*)(vb + (4 * kg    ) * QVS);
            ulonglong2 v1 = *(const ulonglong2*)(vb + (4 * kg + 1) * QVS);
            ulonglong2 v2 = *(const ulonglong2*)(vb + (4 * kg + 2) * QVS);
            ulonglong2 v3 = *(const ulonglong2*)(vb + (4 * kg + 3) * QVS);
            #pragma unroll
            for (int r = 0; r < 7; r++) {
                float4 s4 = *(const float4*)(Sb + r * SS + 4 * kg);
                u64 p;
                p = pack2(s4.x, s4.x);
                att[r][0] = ffma2(p, v0.x, att[r][0]);
                att[r][1] = ffma2(p, v0.y, att[r][1]);
                p = pack2(s4.y, s4.y);
                att[r][0] = ffma2(p, v1.x, att[r][0]);
                att[r][1] = ffma2(p, v1.y, att[r][1]);
                p = pack2(s4.z, s4.z);
                att[r][0] = ffma2(p, v2.x, att[r][0]);
                att[r][1] = ffma2(p, v2.y, att[r][1]);
                p = pack2(s4.w, s4.w);
                att[r][0] = ffma2(p, v3.x, att[r][0]);
                att[r][1] = ffma2(p, v3.y, att[r][1]);
            }
        }

        if (ti < 7) {
            #pragma unroll
            for (int r = 0; r < 7; r++) {
                float inv = rcp(sumr[r]);
                float a0, a1, a2, a3;
                unpack2(att[r][0], a0, a1);
                unpack2(att[r][1], a2, a3);
                float4 o;
                o.x = a0 * inv; o.y = a1 * inv; o.z = a2 * inv; o.w = a3 * inv;
                *(float4*)(out + (size_t)(tok0 + ti * 112 + r) * 384 + cbase + tj * 4) = o;
            }
        }
    }
}

extern "C" void kernel_launch(void* const* d_in, const int* in_sizes, int n_in,
                              void* d_out, int out_size)
{
    const float* qkv = (const float*)d_in[0];
    const float* cw  = (const float*)d_in[1];
    const float* cb  = (const float*)d_in[2];
    float* o = (float*)d_out;
    dim3 grid(4096, 12, 1);
    la_kernel<<<grid, 64>>>(qkv, cw, cb, o);
}

// round 8
// speedup vs baseline: 1.0781x; 1.0781x over previous
#include <cuda_runtime.h>

// LocalAttention: 7x7 windowed MHA + depthwise-3x3 LePE on V.
// grid (4096, 12), 64 threads (8 ti x 8 tj). fp32 via fma.rn.f32x2.
// R7 = R3 structure/config (launch_bounds(64,8), KS=64, simple indexing)
//      + ex2 log2-domain softmax + LePE folded into att accumulator.

typedef unsigned long long u64;

#define QVS 36   // q / v token-major row stride
#define KS  64   // kT row stride (cols 49..63 zero)
#define SS  52   // expS row stride (cols 49..51 zero)

__device__ __forceinline__ u64 pack2(float lo, float hi) {
    u64 r; asm("mov.b64 %0, {%1, %2};" : "=l"(r) : "f"(lo), "f"(hi)); return r;
}
__device__ __forceinline__ void unpack2(u64 v, float &lo, float &hi) {
    asm("mov.b64 {%0, %1}, %2;" : "=f"(lo), "=f"(hi) : "l"(v));
}
__device__ __forceinline__ u64 ffma2(u64 a, u64 b, u64 c) {
    u64 d; asm("fma.rn.f32x2 %0, %1, %2, %3;" : "=l"(d) : "l"(a), "l"(b), "l"(c));
    return d;
}
__device__ __forceinline__ u64 mul2(u64 a, u64 b) {
    u64 d; asm("mul.rn.f32x2 %0, %1, %2;" : "=l"(d) : "l"(a), "l"(b));
    return d;
}
__device__ __forceinline__ float ex2(float x) {
    float y; asm("ex2.approx.ftz.f32 %0, %1;" : "=f"(y) : "f"(x)); return y;
}
__device__ __forceinline__ float rcp(float x) {
    float y; asm("rcp.approx.ftz.f32 %0, %1;" : "=f"(y) : "f"(x)); return y;
}

__global__ __launch_bounds__(64, 8)
void la_kernel(const float* __restrict__ qkv,
               const float* __restrict__ cw,
               const float* __restrict__ cb,
               float* __restrict__ out)
{
    // floats: [0,4064) = union{ qsm[56*36]+kT[32*64] | S[49*52] }
    __shared__ __align__(16) float sm[6256];
    float* qsm = sm;            // [56][QVS] token-major
    float* kT  = sm + 2016;     // [32][KS]
    float* S   = sm;            // [49][SS]  aliases qsm/kT after phase 1
    float* vsm = sm + 4064;     // [52][QVS] rows 49..51 zero
    float* wsm = sm + 5936;     // [9][32]
    float* bsm = sm + 6224;     // [32]

    const int tid = threadIdx.x;
    const int h   = blockIdx.y;
    const int win = blockIdx.x;
    const int b   = win >> 8;
    const int wy  = (win >> 4) & 15;
    const int wx  = win & 15;
    const int tok0  = b * 12544 + wy * 784 + wx * 7;
    const int cbase = h * 32;

    // 1/sqrt(32) * log2(e): softmax runs in log2 domain (ex2.approx)
    const float scale = 0.17677669529663687f * 1.4426950408889634f;
    const size_t koff4 = 19267584ull;           // B*L*DIM/4 (float4 units)

    // zero kT pad cols 49..63
    for (int i = tid; i < 480; i += 64) {
        int d = i / 15;
        kT[d * KS + 49 + (i - d * 15)] = 0.f;
    }
    // zero v pad rows 49..51
    for (int i = tid; i < 108; i += 64) vsm[49 * QVS + i] = 0.f;

    // ---- vectorized load ----
    const float4* qkv4 = (const float4*)qkv;
    for (int idx = tid; idx < 392; idx += 64) {
        int tok = idx >> 3, w = idx & 7;        // d = 4w..4w+3
        int ly = tok / 7, lx = tok - ly * 7;
        size_t g = (size_t)(tok0 + ly * 112 + lx) * 96 + h * 8 + w;
        float4 q4 = qkv4[g];
        float4 k4 = qkv4[g + koff4];
        float4 v4 = qkv4[g + 2 * koff4];
        int d0 = 4 * w;
        q4.x *= scale; q4.y *= scale; q4.z *= scale; q4.w *= scale;
        *(float4*)(qsm + tok * QVS + d0) = q4;
        kT[(d0    ) * KS + tok] = k4.x;
        kT[(d0 + 1) * KS + tok] = k4.y;
        kT[(d0 + 2) * KS + tok] = k4.z;
        kT[(d0 + 3) * KS + tok] = k4.w;
        *(float4*)(vsm + tok * QVS + d0) = v4;
    }
    for (int idx = tid; idx < 288; idx += 64) {
        int tap = idx >> 5, d = idx & 31;
        wsm[tap * 32 + d] = cw[(cbase + d) * 9 + tap];
    }
    if (tid < 32) bsm[tid] = cb[cbase + tid];
    __syncthreads();

    const int ti = tid >> 3;   // 0..7 (rows 7ti..7ti+6; ti==7 pad lane)
    const int tj = tid & 7;    // cols 4tj+{0..3}, 4tj+32+{0..3}

    // ---- phase 1: S = q @ k^T, acc in regs ----
    u64 acc[7][4];
    #pragma unroll
    for (int r = 0; r < 7; r++)
        #pragma unroll
        for (int p = 0; p < 4; p++) acc[r][p] = 0ull;

    {
        const float* qb = qsm + (7 * ti) * QVS;
        const float* kb = kT + (tj << 2);
        #pragma unroll
        for (int dg = 0; dg < 8; dg++) {
            float4 q4[7];
            #pragma unroll
            for (int r = 0; r < 7; r++)
                q4[r] = *(const float4*)(qb + r * QVS + 4 * dg);
            #pragma unroll
            for (int dd = 0; dd < 4; dd++) {
                const float* kr = kb + (4 * dg + dd) * KS;
                ulonglong2 ka = *(const ulonglong2*)(kr);
                ulonglong2 kc = *(const ulonglong2*)(kr + 32);
                #pragma unroll
                for (int r = 0; r < 7; r++) {
                    float qv = (dd == 0) ? q4[r].x : (dd == 1) ? q4[r].y
                             : (dd == 2) ? q4[r].z : q4[r].w;
                    u64 q2 = pack2(qv, qv);
                    acc[r][0] = ffma2(q2, ka.x, acc[r][0]);
                    acc[r][1] = ffma2(q2, ka.y, acc[r][1]);
                    acc[r][2] = ffma2(q2, kc.x, acc[r][2]);
                    acc[r][3] = ffma2(q2, kc.y, acc[r][3]);
                }
            }
        }
    }
    __syncthreads();   // qsm/kT reads done; S may overwrite

    // ---- register softmax (log2 domain) + store expS, keep sum[] in regs ----
    float sumr[7];
    {
        const int c1 = 4 * tj + 32;
        #pragma unroll
        for (int r = 0; r < 7; r++) {
            float s0, s1, s2, s3, s4, s5, s6, s7;
            unpack2(acc[r][0], s0, s1);
            unpack2(acc[r][1], s2, s3);
            unpack2(acc[r][2], s4, s5);
            unpack2(acc[r][3], s6, s7);
            if (c1     >= 49) s4 = -1e30f;
            if (c1 + 1 >= 49) s5 = -1e30f;
            if (c1 + 2 >= 49) s6 = -1e30f;
            if (c1 + 3 >= 49) s7 = -1e30f;
            float m = fmaxf(fmaxf(fmaxf(s0, s1), fmaxf(s2, s3)),
                            fmaxf(fmaxf(s4, s5), fmaxf(s6, s7)));
            m = fmaxf(m, __shfl_xor_sync(0xffffffffu, m, 1));
            m = fmaxf(m, __shfl_xor_sync(0xffffffffu, m, 2));
            m = fmaxf(m, __shfl_xor_sync(0xffffffffu, m, 4));
            float e0 = ex2(s0 - m), e1 = ex2(s1 - m);
            float e2 = ex2(s2 - m), e3 = ex2(s3 - m);
            float e4 = ex2(s4 - m), e5 = ex2(s5 - m);
            float e6 = ex2(s6 - m), e7 = ex2(s7 - m);
            float sum = ((e0 + e1) + (e2 + e3)) + ((e4 + e5) + (e6 + e7));
            sum += __shfl_xor_sync(0xffffffffu, sum, 1);
            sum += __shfl_xor_sync(0xffffffffu, sum, 2);
            sum += __shfl_xor_sync(0xffffffffu, sum, 4);
            sumr[r] = sum;
            if (ti < 7) {
                float* srow = S + (7 * ti + r) * SS;
                *(u64*)(srow + 4 * tj)     = pack2(e0, e1);
                *(u64*)(srow + 4 * tj + 2) = pack2(e2, e3);
                if (c1 < SS) {   // tj<=4: covers cols 32..51 (invalid are 0)
                    *(u64*)(srow + c1)     = pack2(e4, e5);
                    *(u64*)(srow + c1 + 2) = pack2(e6, e7);
                }
            }
        }
    }
    __syncthreads();

    // ---- phase 2: att = (LePE+bias)*sum + expS@V ; out = att * rcp(sum) ----
    {
        u64 att[7][2];
        float4 bb = *(const float4*)(bsm + tj * 4);
        u64 b01 = pack2(bb.x, bb.y), b23 = pack2(bb.z, bb.w);
        #pragma unroll
        for (int r = 0; r < 7; r++) { att[r][0] = b01; att[r][1] = b23; }

        // LePE into att
        #pragma unroll
        for (int ky = 0; ky < 3; ky++) {
            int ny = ti + ky - 1;
            if (ny >= 0 && ny <= 6) {
                #pragma unroll
                for (int kx = 0; kx < 3; kx++) {
                    const ulonglong2 w2 =
                        *(const ulonglong2*)(wsm + (ky * 3 + kx) * 32 + tj * 4);
                    #pragma unroll
                    for (int r = 0; r < 7; r++) {
                        int nx = r + kx - 1;
                        if (nx >= 0 && nx <= 6) {
                            ulonglong2 v2 =
                                *(const ulonglong2*)(vsm + (ny * 7 + nx) * QVS + tj * 4);
                            att[r][0] = ffma2(w2.x, v2.x, att[r][0]);
                            att[r][1] = ffma2(w2.y, v2.y, att[r][1]);
                        }
                    }
                }
            }
        }
        // pre-scale (LePE+bias) by sum so final 1/sum normalizes only attn
        #pragma unroll
        for (int r = 0; r < 7; r++) {
            u64 s2 = pack2(sumr[r], sumr[r]);
            att[r][0] = mul2(att[r][0], s2);
            att[r][1] = mul2(att[r][1], s2);
        }

        // attention: att += expS @ V
        const float* Sb = S + (7 * ti) * SS;
        const float* vb = vsm + (tj << 2);
        #pragma unroll
        for (int kg = 0; kg < 13; kg++) {
            ulonglong2 v0 = *(const ulonglong2*)(vb + (4 * kg    ) * QVS);
            ulonglong2 v1 = *(const ulonglong2*)(vb + (4 * kg + 1) * QVS);
            ulonglong2 v2 = *(const ulonglong2*)(vb + (4 * kg + 2) * QVS);
            ulonglong2 v3 = *(const ulonglong2*)(vb + (4 * kg + 3) * QVS);
            #pragma unroll
            for (int r = 0; r < 7; r++) {
                float4 s4 = *(const float4*)(Sb + r * SS + 4 * kg);
                u64 p;
                p = pack2(s4.x, s4.x);
                att[r][0] = ffma2(p, v0.x, att[r][0]);
                att[r][1] = ffma2(p, v0.y, att[r][1]);
                p = pack2(s4.y, s4.y);
                att[r][0] = ffma2(p, v1.x, att[r][0]);
                att[r][1] = ffma2(p, v1.y, att[r][1]);
                p = pack2(s4.z, s4.z);
                att[r][0] = ffma2(p, v2.x, att[r][0]);
                att[r][1] = ffma2(p, v2.y, att[r][1]);
                p = pack2(s4.w, s4.w);
                att[r][0] = ffma2(p, v3.x, att[r][0]);
                att[r][1] = ffma2(p, v3.y, att[r][1]);
            }
        }

        if (ti < 7) {
            #pragma unroll
            for (int r = 0; r < 7; r++) {
                float iv = rcp(sumr[r]);
                u64 iv2 = pack2(iv, iv);
                u64 lo = mul2(att[r][0], iv2);
                u64 hi = mul2(att[r][1], iv2);
                float4 o;
                unpack2(lo, o.x, o.y);
                unpack2(hi, o.z, o.w);
                *(float4*)(out + (size_t)(tok0 + ti * 112 + r) * 384 + cbase + tj * 4) = o;
            }
        }
    }
}

extern "C" void kernel_launch(void* const* d_in, const int* in_sizes, int n_in,
                              void* d_out, int out_size)
{
    const float* qkv = (const float*)d_in[0];
    const float* cw  = (const float*)d_in[1];
    const float* cb  = (const float*)d_in[2];
    float* o = (float*)d_out;
    dim3 grid(4096, 12, 1);
    la_kernel<<<grid, 64>>>(qkv, cw, cb, o);
}

// round 9
// speedup vs baseline: 1.0790x; 1.0008x over previous
#include <cuda_runtime.h>

// LocalAttention: 7x7 windowed MHA + depthwise-3x3 LePE on V.
// grid (4096, 12), 64 threads (8 ti x 8 tj). fp32 via fma.rn.f32x2.
// R8 = R7 + XOR-swizzled kT layout: physical 16B-block = (tok>>2)^((d>>2)&3).
//      Kills the 8-way bank conflict in the loader's kT transpose scatter.

typedef unsigned long long u64;

#define QVS 36   // q / v token-major row stride
#define KS  64   // kT row stride (16 blocks of 16B; logical cols 49..63 zero)
#define SS  52   // expS row stride (cols 49..51 zero)

__device__ __forceinline__ u64 pack2(float lo, float hi) {
    u64 r; asm("mov.b64 %0, {%1, %2};" : "=l"(r) : "f"(lo), "f"(hi)); return r;
}
__device__ __forceinline__ void unpack2(u64 v, float &lo, float &hi) {
    asm("mov.b64 {%0, %1}, %2;" : "=f"(lo), "=f"(hi) : "l"(v));
}
__device__ __forceinline__ u64 ffma2(u64 a, u64 b, u64 c) {
    u64 d; asm("fma.rn.f32x2 %0, %1, %2, %3;" : "=l"(d) : "l"(a), "l"(b), "l"(c));
    return d;
}
__device__ __forceinline__ u64 mul2(u64 a, u64 b) {
    u64 d; asm("mul.rn.f32x2 %0, %1, %2;" : "=l"(d) : "l"(a), "l"(b));
    return d;
}
__device__ __forceinline__ float ex2(float x) {
    float y; asm("ex2.approx.ftz.f32 %0, %1;" : "=f"(y) : "f"(x)); return y;
}
__device__ __forceinline__ float rcp(float x) {
    float y; asm("rcp.approx.ftz.f32 %0, %1;" : "=f"(y) : "f"(x)); return y;
}

__global__ __launch_bounds__(64, 8)
void la_kernel(const float* __restrict__ qkv,
               const float* __restrict__ cw,
               const float* __restrict__ cb,
               float* __restrict__ out)
{
    // floats: [0,4064) = union{ qsm[56*36]+kT[32*64] | S[49*52] }
    __shared__ __align__(16) float sm[6256];
    float* qsm = sm;            // [56][QVS] token-major
    float* kT  = sm + 2016;     // [32][KS]  d-major, token blocks XOR-swizzled
    float* S   = sm;            // [49][SS]  aliases qsm/kT after phase 1
    float* vsm = sm + 4064;     // [52][QVS] rows 49..51 zero
    float* wsm = sm + 5936;     // [9][32]
    float* bsm = sm + 6224;     // [32]

    const int tid = threadIdx.x;
    const int h   = blockIdx.y;
    const int win = blockIdx.x;
    const int b   = win >> 8;
    const int wy  = (win >> 4) & 15;
    const int wx  = win & 15;
    const int tok0  = b * 12544 + wy * 784 + wx * 7;
    const int cbase = h * 32;

    // 1/sqrt(32) * log2(e): softmax runs in log2 domain (ex2.approx)
    const float scale = 0.17677669529663687f * 1.4426950408889634f;
    const size_t koff4 = 19267584ull;           // B*L*DIM/4 (float4 units)

    // zero kT pad: logical cols 49..63, at swizzled physical addresses
    for (int i = tid; i < 480; i += 64) {
        int d = i / 15;
        int c = 49 + (i - d * 15);
        int key = (d >> 2) & 3;
        int pcol = ((((c >> 2) ^ key) << 2)) | (c & 3);
        kT[d * KS + pcol] = 0.f;
    }
    // zero v pad rows 49..51
    for (int i = tid; i < 108; i += 64) vsm[49 * QVS + i] = 0.f;

    // ---- vectorized load ----
    const float4* qkv4 = (const float4*)qkv;
    for (int idx = tid; idx < 392; idx += 64) {
        int tok = idx >> 3, w = idx & 7;        // d = 4w..4w+3
        int ly = tok / 7, lx = tok - ly * 7;
        size_t g = (size_t)(tok0 + ly * 112 + lx) * 96 + h * 8 + w;
        float4 q4 = qkv4[g];
        float4 k4 = qkv4[g + koff4];
        float4 v4 = qkv4[g + 2 * koff4];
        int d0 = 4 * w;
        q4.x *= scale; q4.y *= scale; q4.z *= scale; q4.w *= scale;
        *(float4*)(qsm + tok * QVS + d0) = q4;
        // swizzled kT store: key = (d>>2)&3 = w&3 for all 4 components
        int pcol = ((((tok >> 2) ^ (w & 3)) << 2)) | (tok & 3);
        kT[(d0    ) * KS + pcol] = k4.x;
        kT[(d0 + 1) * KS + pcol] = k4.y;
        kT[(d0 + 2) * KS + pcol] = k4.z;
        kT[(d0 + 3) * KS + pcol] = k4.w;
        *(float4*)(vsm + tok * QVS + d0) = v4;
    }
    for (int idx = tid; idx < 288; idx += 64) {
        int tap = idx >> 5, d = idx & 31;
        wsm[tap * 32 + d] = cw[(cbase + d) * 9 + tap];
    }
    if (tid < 32) bsm[tid] = cb[cbase + tid];
    __syncthreads();

    const int ti = tid >> 3;   // 0..7 (rows 7ti..7ti+6; ti==7 pad lane)
    const int tj = tid & 7;    // cols 4tj+{0..3}, 4tj+32+{0..3}

    // ---- phase 1: S = q @ k^T, acc in regs ----
    u64 acc[7][4];
    #pragma unroll
    for (int r = 0; r < 7; r++)
        #pragma unroll
        for (int p = 0; p < 4; p++) acc[r][p] = 0ull;

    {
        const float* qb = qsm + (7 * ti) * QVS;
        #pragma unroll
        for (int dg = 0; dg < 8; dg++) {
            float4 q4[7];
            #pragma unroll
            for (int r = 0; r < 7; r++)
                q4[r] = *(const float4*)(qb + r * QVS + 4 * dg);
            // swizzled base: logical block tj -> physical block tj^(dg&3)
            const float* kb = kT + ((tj ^ (dg & 3)) << 2);
            #pragma unroll
            for (int dd = 0; dd < 4; dd++) {
                const float* kr = kb + (4 * dg + dd) * KS;
                ulonglong2 ka = *(const ulonglong2*)(kr);        // logical cols 4tj..
                ulonglong2 kc = *(const ulonglong2*)(kr + 32);   // logical cols 4tj+32..
                #pragma unroll
                for (int r = 0; r < 7; r++) {
                    float qv = (dd == 0) ? q4[r].x : (dd == 1) ? q4[r].y
                             : (dd == 2) ? q4[r].z : q4[r].w;
                    u64 q2 = pack2(qv, qv);
                    acc[r][0] = ffma2(q2, ka.x, acc[r][0]);
                    acc[r][1] = ffma2(q2, ka.y, acc[r][1]);
                    acc[r][2] = ffma2(q2, kc.x, acc[r][2]);
                    acc[r][3] = ffma2(q2, kc.y, acc[r][3]);
                }
            }
        }
    }
    __syncthreads();   // qsm/kT reads done; S may overwrite

    // ---- register softmax (log2 domain) + store expS, keep sum[] in regs ----
    float sumr[7];
    {
        const int c1 = 4 * tj + 32;
        #pragma unroll
        for (int r = 0; r < 7; r++) {
            float s0, s1, s2, s3, s4, s5, s6, s7;
            unpack2(acc[r][0], s0, s1);
            unpack2(acc[r][1], s2, s3);
            unpack2(acc[r][2], s4, s5);
            unpack2(acc[r][3], s6, s7);
            if (c1     >= 49) s4 = -1e30f;
            if (c1 + 1 >= 49) s5 = -1e30f;
            if (c1 + 2 >= 49) s6 = -1e30f;
            if (c1 + 3 >= 49) s7 = -1e30f;
            float m = fmaxf(fmaxf(fmaxf(s0, s1), fmaxf(s2, s3)),
                            fmaxf(fmaxf(s4, s5), fmaxf(s6, s7)));
            m = fmaxf(m, __shfl_xor_sync(0xffffffffu, m, 1));
            m = fmaxf(m, __shfl_xor_sync(0xffffffffu, m, 2));
            m = fmaxf(m, __shfl_xor_sync(0xffffffffu, m, 4));
            float e0 = ex2(s0 - m), e1 = ex2(s1 - m);
            float e2 = ex2(s2 - m), e3 = ex2(s3 - m);
            float e4 = ex2(s4 - m), e5 = ex2(s5 - m);
            float e6 = ex2(s6 - m), e7 = ex2(s7 - m);
            float sum = ((e0 + e1) + (e2 + e3)) + ((e4 + e5) + (e6 + e7));
            sum += __shfl_xor_sync(0xffffffffu, sum, 1);
            sum += __shfl_xor_sync(0xffffffffu, sum, 2);
            sum += __shfl_xor_sync(0xffffffffu, sum, 4);
            sumr[r] = sum;
            if (ti < 7) {
                float* srow = S + (7 * ti + r) * SS;
                *(u64*)(srow + 4 * tj)     = pack2(e0, e1);
                *(u64*)(srow + 4 * tj + 2) = pack2(e2, e3);
                if (c1 < SS) {   // tj<=4: covers cols 32..51 (invalid are 0)
                    *(u64*)(srow + c1)     = pack2(e4, e5);
                    *(u64*)(srow + c1 + 2) = pack2(e6, e7);
                }
            }
        }
    }
    __syncthreads();

    // ---- phase 2: att = (LePE+bias)*sum + expS@V ; out = att * rcp(sum) ----
    {
        u64 att[7][2];
        float4 bb = *(const float4*)(bsm + tj * 4);
        u64 b01 = pack2(bb.x, bb.y), b23 = pack2(bb.z, bb.w);
        #pragma unroll
        for (int r = 0; r < 7; r++) { att[r][0] = b01; att[r][1] = b23; }

        // LePE into att
        #pragma unroll
        for (int ky = 0; ky < 3; ky++) {
            int ny = ti + ky - 1;
            if (ny >= 0 && ny <= 6) {
                #pragma unroll
                for (int kx = 0; kx < 3; kx++) {
                    const ulonglong2 w2 =
                        *(const ulonglong2*)(wsm + (ky * 3 + kx) * 32 + tj * 4);
                    #pragma unroll
                    for (int r = 0; r < 7; r++) {
                        int nx = r + kx - 1;
                        if (nx >= 0 && nx <= 6) {
                            ulonglong2 v2 =
                                *(const ulonglong2*)(vsm + (ny * 7 + nx) * QVS + tj * 4);
                            att[r][0] = ffma2(w2.x, v2.x, att[r][0]);
                            att[r][1] = ffma2(w2.y, v2.y, att[r][1]);
                        }
                    }
                }
            }
        }
        // pre-scale (LePE+bias) by sum so final 1/sum normalizes only attn
        #pragma unroll
        for (int r = 0; r < 7; r++) {
            u64 s2 = pack2(sumr[r], sumr[r]);
            att[r][0] = mul2(att[r][0], s2);
            att[r][1] = mul2(att[r][1], s2);
        }

        // attention: att += expS @ V
        const float* Sb = S + (7 * ti) * SS;
        const float* vb = vsm + (tj << 2);
        #pragma unroll
        for (int kg = 0; kg < 13; kg++) {
            ulonglong2 v0 = *(const ulonglong2*)(vb + (4 * kg    ) * QVS);
            ulonglong2 v1 = *(const ulonglong2*)(vb + (4 * kg + 1) * QVS);
            ulonglong2 v2 = *(const ulonglong2*)(vb + (4 * kg + 2) * QVS);
            ulonglong2 v3 = *(const ulonglong2*)(vb + (4 * kg + 3) * QVS);
            #pragma unroll
            for (int r = 0; r < 7; r++) {
                float4 s4 = *(const float4*)(Sb + r * SS + 4 * kg);
                u64 p;
                p = pack2(s4.x, s4.x);
                att[r][0] = ffma2(p, v0.x, att[r][0]);
                att[r][1] = ffma2(p, v0.y, att[r][1]);
                p = pack2(s4.y, s4.y);
                att[r][0] = ffma2(p, v1.x, att[r][0]);
                att[r][1] = ffma2(p, v1.y, att[r][1]);
                p = pack2(s4.z, s4.z);
                att[r][0] = ffma2(p, v2.x, att[r][0]);
                att[r][1] = ffma2(p, v2.y, att[r][1]);
                p = pack2(s4.w, s4.w);
                att[r][0] = ffma2(p, v3.x, att[r][0]);
                att[r][1] = ffma2(p, v3.y, att[r][1]);
            }
        }

        if (ti < 7) {
            #pragma unroll
            for (int r = 0; r < 7; r++) {
                float iv = rcp(sumr[r]);
                u64 iv2 = pack2(iv, iv);
                u64 lo = mul2(att[r][0], iv2);
                u64 hi = mul2(att[r][1], iv2);
                float4 o;
                unpack2(lo, o.x, o.y);
                unpack2(hi, o.z, o.w);
                *(float4*)(out + (size_t)(tok0 + ti * 112 + r) * 384 + cbase + tj * 4) = o;
            }
        }
    }
}

extern "C" void kernel_launch(void* const* d_in, const int* in_sizes, int n_in,
                              void* d_out, int out_size)
{
    const float* qkv = (const float*)d_in[0];
    const float* cw  = (const float*)d_in[1];
    const float* cb  = (const float*)d_in[2];
    float* o = (float*)d_out;
    dim3 grid(4096, 12, 1);
    la_kernel<<<grid, 64>>>(qkv, cw, cb, o);
}